// round 3
// baseline (speedup 1.0000x reference)
#include <cuda_runtime.h>
#include <cuda_bf16.h>
#include <math.h>

// Problem constants (fixed by the reference)
#define N_DIM 8192
#define E_CNT 262144
#define EPS 1e-8f

#define THREADS 256
#define BLOCKS  512   // E/2 edges-per-thread pairs: 512*256 = 131072 = E/2 exactly

// Scratch (no cudaMalloc allowed). Partial slots are fully rewritten every
// run; the ticket is reset to 0 by the last block, so the kernel is
// deterministic and graph-replay-safe.
__device__ float g_part_pos[BLOCKS];
__device__ float g_part_neg[BLOCKS];
__device__ unsigned int g_ticket;   // zero-initialized at load

__global__ __launch_bounds__(THREADS) void fused_loss_kernel(
    const float* __restrict__ adj,        // [8192, 8192]
    const int* __restrict__ edge_index,   // [2, E]: src at [0..E), dst at [E..2E)
    const int* __restrict__ neg_edges,    // [E, 2] interleaved
    const float* __restrict__ codebook,   // [6]
    float* __restrict__ out)
{
    const int t = blockIdx.x * THREADS + threadIdx.x;   // 0 .. E/2-1
    const int i = 2 * t;

    // Coalesced vector index loads
    int2 src2 = __ldg((const int2*)&edge_index[i]);
    int2 dst2 = __ldg((const int2*)&edge_index[E_CNT + i]);
    int4 neg4 = __ldg((const int4*)&neg_edges[2 * i]);

    // 4 independent random gathers in flight (MLP=4)
    float pv0 = __ldg(&adj[(long long)src2.x * N_DIM + dst2.x]);
    float pv1 = __ldg(&adj[(long long)src2.y * N_DIM + dst2.y]);
    float nv0 = __ldg(&adj[(long long)neg4.x * N_DIM + neg4.y]);
    float nv1 = __ldg(&adj[(long long)neg4.z * N_DIM + neg4.w]);

    float pos_term = __logf(pv0 + EPS) + __logf(pv1 + EPS);
    float neg_term = __logf(1.0f - nv0 + EPS) + __logf(1.0f - nv1 + EPS);

    // ---- block reduction ----
    #pragma unroll
    for (int off = 16; off > 0; off >>= 1) {
        pos_term += __shfl_down_sync(0xFFFFFFFFu, pos_term, off);
        neg_term += __shfl_down_sync(0xFFFFFFFFu, neg_term, off);
    }

    __shared__ float s_pos[8];
    __shared__ float s_neg[8];
    __shared__ bool  s_is_last;
    const int lane = threadIdx.x & 31;
    const int wid  = threadIdx.x >> 5;
    if (lane == 0) { s_pos[wid] = pos_term; s_neg[wid] = neg_term; }
    __syncthreads();

    if (wid == 0) {
        float p = (lane < 8) ? s_pos[lane] : 0.0f;
        float n = (lane < 8) ? s_neg[lane] : 0.0f;
        #pragma unroll
        for (int off = 4; off > 0; off >>= 1) {
            p += __shfl_down_sync(0xFFFFFFFFu, p, off);
            n += __shfl_down_sync(0xFFFFFFFFu, n, off);
        }
        if (lane == 0) {
            g_part_pos[blockIdx.x] = p;
            g_part_neg[blockIdx.x] = n;
            __threadfence();
            unsigned int ticket = atomicInc(&g_ticket, BLOCKS - 1);
            s_is_last = (ticket == BLOCKS - 1);
        }
    }
    __syncthreads();

    // ---- last block: final reduce + epilogue ----
    if (s_is_last) {
        __threadfence();   // ensure all partials are visible
        // 512 slots / 256 threads = 2 each
        float p = g_part_pos[threadIdx.x] + g_part_pos[threadIdx.x + THREADS];
        float n = g_part_neg[threadIdx.x] + g_part_neg[threadIdx.x + THREADS];

        #pragma unroll
        for (int off = 16; off > 0; off >>= 1) {
            p += __shfl_down_sync(0xFFFFFFFFu, p, off);
            n += __shfl_down_sync(0xFFFFFFFFu, n, off);
        }
        if (lane == 0) { s_pos[wid] = p; s_neg[wid] = n; }
        __syncthreads();
        if (wid == 0) {
            float pp = (lane < 8) ? s_pos[lane] : 0.0f;
            float nn = (lane < 8) ? s_neg[lane] : 0.0f;
            #pragma unroll
            for (int off = 4; off > 0; off >>= 1) {
                pp += __shfl_down_sync(0xFFFFFFFFu, pp, off);
                nn += __shfl_down_sync(0xFFFFFFFFu, nn, off);
            }
            if (lane == 0) {
                float pos_loss = -pp * (1.0f / (float)E_CNT);
                float neg_loss = -nn * (1.0f / (float)E_CNT);
                out[0] = pos_loss + neg_loss
                       + codebook[0] + codebook[1] + codebook[2] + codebook[3];
                // atomicInc with wrap (BLOCKS-1) already returned g_ticket to 0
                // on the last increment, but be explicit for safety:
                g_ticket = 0u;
            }
        }
    }
}

extern "C" void kernel_launch(void* const* d_in, const int* in_sizes, int n_in,
                              void* d_out, int out_size) {
    const float* adj       = (const float*)d_in[0];   // [8192, 8192] f32
    const float* codebook  = (const float*)d_in[1];   // [6] f32
    const int*   edge_idx  = (const int*)d_in[2];     // [2, E] i32
    const int*   neg_edges = (const int*)d_in[3];     // [E, 2] i32
    float*       out       = (float*)d_out;

    fused_loss_kernel<<<BLOCKS, THREADS>>>(adj, edge_idx, neg_edges, codebook, out);
}